// round 6
// baseline (speedup 1.0000x reference)
#include <cuda_runtime.h>
#include <cuda_bf16.h>

// AvgPool over last 4 dims of [2,16,32,32,32,32], kernel=stride=2, pad=0.
// Collapsed: N = 2*16 rows of a [32,32,32,32] tensor -> out [N,16,16,16,16].
//
// R3 mapping (ncu-fastest) + streaming cache hints (harness-fastest):
// each thread produces one float2 of output (2 adjacent outputs along d4),
// reading 8 independent float4s — one per (d1,d2,d3) window corner in {0,1}^3.
// Warp lanes p=0..7 make each corner's requests a dense 128B segment, and the
// base / base+S_D3 pair tiles a contiguous 256B span. Read-once/write-once
// stream -> __ldcs/__stcs evict-first to keep L2 out of the way.

// Input strides in float4 units (D4 = 32 floats = 8 float4 per row)
static constexpr int S_N  = 262144;  // 32^4 / 4
static constexpr int S_D1 = 8192;    // 32^3 / 4
static constexpr int S_D2 = 256;     // 32^2 / 4
static constexpr int S_D3 = 8;       // 32   / 4

__global__ void __launch_bounds__(256)
avgpool4d_kernel(const float4* __restrict__ in, float2* __restrict__ out,
                 int n_pairs)
{
    int tid = blockIdx.x * blockDim.x + threadIdx.x;
    if (tid >= n_pairs) return;

    // tid -> (n, o1, o2, o3, p); p = output-pair index along d4 (0..7)
    int p  =  tid        & 7;
    int o3 = (tid >> 3)  & 15;
    int o2 = (tid >> 7)  & 15;
    int o1 = (tid >> 11) & 15;
    int n  =  tid >> 15;

    // Base float4 index of the window origin
    const float4* b = in + (n * S_N + (2 * o1) * S_D1 + (2 * o2) * S_D2
                            + (2 * o3) * S_D3 + p);

    // 8 independent streaming loads, front-batched for MLP
    float4 v0 = __ldcs(b);
    float4 v1 = __ldcs(b + S_D3);
    float4 v2 = __ldcs(b + S_D2);
    float4 v3 = __ldcs(b + S_D2 + S_D3);
    float4 v4 = __ldcs(b + S_D1);
    float4 v5 = __ldcs(b + S_D1 + S_D3);
    float4 v6 = __ldcs(b + S_D1 + S_D2);
    float4 v7 = __ldcs(b + S_D1 + S_D2 + S_D3);

    float lo = (v0.x + v0.y) + (v1.x + v1.y)
             + (v2.x + v2.y) + (v3.x + v3.y)
             + (v4.x + v4.y) + (v5.x + v5.y)
             + (v6.x + v6.y) + (v7.x + v7.y);
    float hi = (v0.z + v0.w) + (v1.z + v1.w)
             + (v2.z + v2.w) + (v3.z + v3.w)
             + (v4.z + v4.w) + (v5.z + v5.w)
             + (v6.z + v6.w) + (v7.z + v7.w);

    const float scale = 1.0f / 16.0f;
    __stcs(out + tid, make_float2(lo * scale, hi * scale));
}

extern "C" void kernel_launch(void* const* d_in, const int* in_sizes, int n_in,
                              void* d_out, int out_size)
{
    (void)in_sizes; (void)n_in;
    const float4* in = (const float4*)d_in[0];
    float2* out = (float2*)d_out;

    int n_pairs = out_size / 2;               // one float2 per thread
    int threads = 256;
    int blocks  = (n_pairs + threads - 1) / threads;  // 4096 for the ref shape
    avgpool4d_kernel<<<blocks, threads>>>(in, out, n_pairs);
}